// round 6
// baseline (speedup 1.0000x reference)
#include <cuda_runtime.h>
#include <math.h>

#define NB 4
#define TDIM 8
#define LP1 197
#define HH 12
#define DD 64
#define CC 768
#define LL 196
#define NT 28   // NB*(TDIM-1)

typedef unsigned long long u64;

__device__ __forceinline__ u64 pk2(float lo, float hi) {
    u64 r; asm("mov.b64 %0,{%1,%2};" : "=l"(r) : "f"(lo), "f"(hi)); return r;
}
__device__ __forceinline__ void upk2(u64 v, float& lo, float& hi) {
    asm("mov.b64 {%0,%1},%2;" : "=f"(lo), "=f"(hi) : "l"(v));
}
__device__ __forceinline__ u64 ffma2(u64 a, u64 b, u64 c) {
    u64 d; asm("fma.rn.f32x2 %0,%1,%2,%3;" : "=l"(d) : "l"(a), "l"(b), "l"(c)); return d;
}
__device__ __forceinline__ u64 fadd2(u64 a, u64 b) {
    u64 d; asm("add.rn.f32x2 %0,%1,%2;" : "=l"(d) : "l"(a), "l"(b)); return d;
}
__device__ __forceinline__ void red2(float* p, float a, float b) {
    asm volatile("red.global.add.v2.f32 [%0], {%1,%2};" :: "l"(p), "f"(a), "f"(b) : "memory");
}

// Scratch: head-averaged attention probabilities for each half.
__device__ float g_P1[NT * LL * LL];
__device__ float g_P2[NT * LL * LL];

// ---------------------------------------------------------------------------
// Kernel 0: zero P scratch and the cls (q=0) rows of out.
// ---------------------------------------------------------------------------
__global__ void zero_kernel(float* __restrict__ out) {
    size_t stride = (size_t)gridDim.x * blockDim.x;
    size_t i = (size_t)blockIdx.x * blockDim.x + threadIdx.x;
    const size_t np = (size_t)NT * LL * LL;
    for (size_t j = i; j < np; j += stride) { g_P1[j] = 0.f; g_P2[j] = 0.f; }
    const size_t ncls = (size_t)NB * TDIM * CC;
    for (size_t j = i; j < ncls; j += stride) {
        size_t nt = j / CC, c = j - nt * CC;
        out[(nt * LP1) * CC + c] = 0.f;
    }
}

// ---------------------------------------------------------------------------
// Kernel 1: attention, 3-heads-per-block register accumulation.
// Block = (qh:7, nt:28, h3*2+half:8).  256 threads (16x16), 2 CTAs/SM.
// Per block: 28 q-rows; loop hh=0..2 (head h3*3+hh): load K tile + Q chunk,
// f32x2 GEMM (2 rows x 7 col-pairs/thread), register softmax per row
// (half-warp shfl), accumulate e*(1/12/s) into persistent accP registers.
// ONE red2 per element at the end -> 4x fewer global atomics than per-head.
// ---------------------------------------------------------------------------
#define KS_STRIDE 210
#define QS2_STRIDE 33
#define A_SMEM_BYTES ((64*KS_STRIDE + 64*QS2_STRIDE) * 4)   // 62208 B

__global__ __launch_bounds__(256, 2)
void attn_kernel(const float* __restrict__ q, const float* __restrict__ k) {
    extern __shared__ float sm[];
    float* ks = sm;                          // [64][210]
    float* qs = ks + 64 * KS_STRIDE;         // [64][33]  (28 rows used)

    int qh   = blockIdx.x;          // 0..6  -> q rows [qh*28, qh*28+28)
    int nt   = blockIdx.y;
    int zh   = blockIdx.z;          // 0..7
    int h3   = zh >> 1;             // head triple
    int half = zh & 1;
    int n = nt / 7, t = nt - n * 7;
    int tq = (half == 0) ? t + 1 : t;
    int tk = (half == 0) ? t : t + 1;
    int q0 = qh * 28;

    const float* qb0 = q + ((size_t)(n * TDIM + tq) * LP1 + 1) * (HH * DD);
    const float* kb0 = k + ((size_t)(n * TDIM + tk) * LP1 + 1) * (HH * DD);
    float* P = ((half == 0) ? g_P1 : g_P2) + (size_t)nt * LL * LL;

    int tid = threadIdx.x;
    int tx = tid & 15, ty = tid >> 4;

    u64 accP[2][7];
    #pragma unroll
    for (int a = 0; a < 2; a++)
        #pragma unroll
        for (int b = 0; b < 7; b++) accP[a][b] = 0ULL;

    for (int hh = 0; hh < 3; hh++) {
        int h = h3 * 3 + hh;
        const float* kb = kb0 + h * DD;
        const float* qb = qb0 + h * DD;

        __syncthreads();   // prior iteration's reads of ks/qs complete

        // K tile transposed: ks[d][kk] = k[kk][d]
        for (int i = tid; i < LL * DD; i += 256) {
            int kk = i >> 6, d = i & 63;
            ks[d * KS_STRIDE + kk] = kb[(size_t)kk * (HH * DD) + d];
        }
        // Q chunk (28 rows) transposed, pre-scaled
        for (int i = tid; i < 28 * DD; i += 256) {
            int qq = i >> 6, d = i & 63;
            qs[d * QS2_STRIDE + qq] = qb[(size_t)(q0 + qq) * (HH * DD) + d] * 0.125f;
        }
        __syncthreads();

        // 28(32)x196 GEMM over K=64: 2 rows x 7 col-pairs per thread
        u64 acc[2][7];
        #pragma unroll
        for (int a = 0; a < 2; a++)
            #pragma unroll
            for (int b = 0; b < 7; b++) acc[a][b] = 0ULL;

        #pragma unroll 4
        for (int d = 0; d < 64; d++) {
            u64 ad[2], bv[7];
            #pragma unroll
            for (int a = 0; a < 2; a++) {
                float av = qs[d * QS2_STRIDE + ty + 16 * a];
                ad[a] = pk2(av, av);
            }
            #pragma unroll
            for (int b = 0; b < 7; b++)
                bv[b] = *(const u64*)&ks[d * KS_STRIDE + 2 * tx + 32 * b];
            #pragma unroll
            for (int a = 0; a < 2; a++)
                #pragma unroll
                for (int b = 0; b < 7; b++)
                    acc[a][b] = ffma2(ad[a], bv[b], acc[a][b]);
        }

        // Register softmax per row (half-warp owns a row), accumulate into accP.
        #pragma unroll
        for (int a = 0; a < 2; a++) {
            float e[14];
            #pragma unroll
            for (int b = 0; b < 7; b++) upk2(acc[a][b], e[2 * b], e[2 * b + 1]);

            bool v6 = (tx < 2);
            float mx = -1e30f;
            #pragma unroll
            for (int b = 0; b < 6; b++) mx = fmaxf(mx, fmaxf(e[2 * b], e[2 * b + 1]));
            if (v6) mx = fmaxf(mx, fmaxf(e[12], e[13]));
            #pragma unroll
            for (int off = 8; off > 0; off >>= 1)
                mx = fmaxf(mx, __shfl_xor_sync(0xffffffffu, mx, off));

            float s = 0.f;
            #pragma unroll
            for (int b = 0; b < 6; b++) {
                e[2 * b]     = __expf(e[2 * b] - mx);
                e[2 * b + 1] = __expf(e[2 * b + 1] - mx);
                s += e[2 * b] + e[2 * b + 1];
            }
            if (v6) {
                e[12] = __expf(e[12] - mx);
                e[13] = __expf(e[13] - mx);
                s += e[12] + e[13];
            }
            #pragma unroll
            for (int off = 8; off > 0; off >>= 1)
                s += __shfl_xor_sync(0xffffffffu, s, off);

            float inv = (1.f / 12.f) / s;
            u64 iv = pk2(inv, inv);
            #pragma unroll
            for (int b = 0; b < 7; b++)
                accP[a][b] = ffma2(pk2(e[2 * b], e[2 * b + 1]), iv, accP[a][b]);
        }
    }

    // Single atomic accumulate into P (only 4 h3-blocks contend).
    #pragma unroll
    for (int a = 0; a < 2; a++) {
        int r = ty + 16 * a;
        if (r < 28) {
            float* Pr = P + (size_t)(q0 + r) * LL + 2 * tx;
            #pragma unroll
            for (int b = 0; b < 6; b++) {
                float lo, hi; upk2(accP[a][b], lo, hi);
                red2(Pr + 32 * b, lo, hi);
            }
            if (tx < 2) {
                float lo, hi; upk2(accP[a][6], lo, hi);
                red2(Pr + 192, lo, hi);
            }
        }
    }
}

// ---------------------------------------------------------------------------
// Kernel 2 (fused halves) — ROUND-4 VERSION (reverted; R5 variant regressed).
// out[n,tt,q+1,c] = sum_k P1[n,tt-1,q,k]*w1[IDX[q,k],c]
//                 + sum_k P2[n,tt  ,q,k]*w2[IDX[q,k],c]
// ---------------------------------------------------------------------------
#define TCo 64
#define WS_FLOATS (98 * TCo)            // 6272
#define PS_FLOATS (2 * LL * 8)          // 3136 per half
#define O_SMEM_BYTES ((WS_FLOATS + 2 * PS_FLOATS) * 4)   // 50176 B

__global__ __launch_bounds__(256, 4)
void out_kernel(const float* __restrict__ w1, const float* __restrict__ w2,
                float* __restrict__ out) {
    extern __shared__ float sm[];
    float* ws  = sm;                    // [98][64]
    float* psA = sm + WS_FLOATS;        // [2][196*8]  slot tt = P1[t=tt-1], slot0=0
    float* psB = psA + PS_FLOATS;       // [2][196*8]  slot tt = P2[tt],    slot7=0

    int qq = blockIdx.y;
    int c0 = blockIdx.x * TCo;
    int np = blockIdx.z;
    int tid = threadIdx.x;
    int pi = qq / 14, pj = qq - pi * 14;

    #pragma unroll
    for (int r = 0; r < 14; r++) {
        int n_l = r / 7, t = r - n_l * 7;
        if (tid < LL) {
            int n = np * 2 + n_l;
            size_t base = ((size_t)(n * 7 + t) * LL + qq) * LL + tid;
            psA[n_l * (LL * 8) + tid * 8 + t + 1] = g_P1[base];
            psB[n_l * (LL * 8) + tid * 8 + t]     = g_P2[base];
        }
    }
    if (tid < LL) {
        psA[tid * 8] = 0.f;            psA[LL * 8 + tid * 8] = 0.f;
        psB[tid * 8 + 7] = 0.f;        psB[LL * 8 + tid * 8 + 7] = 0.f;
    }

    int wid = tid >> 5, lane = tid & 31;
    int n_l = wid >> 2, kq = wid & 3;
    int kst = kq * 25 - ((kq > 2) ? (kq - 2) : 0);
    int kcn = 25 - (kq >= 2 ? 1 : 0);

    u64 acc[8];   // [tp][cpart]
    #pragma unroll
    for (int i = 0; i < 8; i++) acc[i] = 0ULL;

    #pragma unroll
    for (int ph = 0; ph < 4; ph++) {
        const float* w = (ph < 2) ? w1 : w2;
        const float* ps = ((ph < 2) ? psA : psB) + n_l * (LL * 8);
        int kbase = (ph & 1) * 98;

        __syncthreads();
        for (int i = tid; i < 98 * 16; i += 256) {
            int kk = i >> 4, cq = i & 15;
            int kg = kbase + kk;
            int ki = kg / 14, kj = kg - ki * 14;
            int idx = (pi - ki + 13) * 27 + (pj - kj + 13);
            *(float4*)&ws[kk * TCo + cq * 4] =
                *(const float4*)(w + (size_t)idx * CC + c0 + cq * 4);
        }
        __syncthreads();

        #pragma unroll 5
        for (int kl = kst; kl < kst + kcn; kl++) {
            float2 wv = *(const float2*)&ws[kl * TCo + 2 * lane];
            u64 b0 = pk2(wv.x, wv.x), b1 = pk2(wv.y, wv.y);
            const u64* pp = (const u64*)&ps[(kbase + kl) * 8];
            u64 p0 = pp[0], p1 = pp[1], p2 = pp[2], p3 = pp[3];
            acc[0] = ffma2(p0, b0, acc[0]);  acc[1] = ffma2(p0, b1, acc[1]);
            acc[2] = ffma2(p1, b0, acc[2]);  acc[3] = ffma2(p1, b1, acc[3]);
            acc[4] = ffma2(p2, b0, acc[4]);  acc[5] = ffma2(p2, b1, acc[5]);
            acc[6] = ffma2(p3, b0, acc[6]);  acc[7] = ffma2(p3, b1, acc[7]);
        }
    }

    __syncthreads();
    u64* red = (u64*)ws;
    if (kq) {
        int base = ((n_l * 3 + (kq - 1)) * 32 + lane) * 8;
        #pragma unroll
        for (int j = 0; j < 8; j++) red[base + j] = acc[j];
    }
    __syncthreads();

    if (kq == 0) {
        #pragma unroll
        for (int ww = 0; ww < 3; ww++) {
            int base = ((n_l * 3 + ww) * 32 + lane) * 8;
            #pragma unroll
            for (int j = 0; j < 8; j++) acc[j] = fadd2(acc[j], red[base + j]);
        }
        int n = np * 2 + n_l;
        float a[16];
        #pragma unroll
        for (int i = 0; i < 8; i++) upk2(acc[i], a[2 * i], a[2 * i + 1]);
        #pragma unroll
        for (int tt = 0; tt < 8; tt++) {
            int tp = tt >> 1, hi = tt & 1;
            float2 o2;
            o2.x = a[(tp * 2 + 0) * 2 + hi];
            o2.y = a[(tp * 2 + 1) * 2 + hi];
            *(float2*)(out + ((size_t)(n * TDIM + tt) * LP1 + qq + 1) * CC
                       + c0 + 2 * lane) = o2;
        }
    }
}

// ---------------------------------------------------------------------------
extern "C" void kernel_launch(void* const* d_in, const int* in_sizes, int n_in,
                              void* d_out, int out_size) {
    const float* q  = (const float*)d_in[0];
    const float* k  = (const float*)d_in[1];
    const float* w1 = (const float*)d_in[2];
    const float* w2 = (const float*)d_in[3];
    float* out = (float*)d_out;

    cudaFuncSetAttribute(attn_kernel, cudaFuncAttributeMaxDynamicSharedMemorySize, A_SMEM_BYTES);
    cudaFuncSetAttribute(out_kernel,  cudaFuncAttributeMaxDynamicSharedMemorySize, O_SMEM_BYTES);

    zero_kernel<<<512, 256>>>(out);
    attn_kernel<<<dim3(7, NT, 8), 256, A_SMEM_BYTES>>>(q, k);
    out_kernel<<<dim3(CC / TCo, LL, NB / 2), 256, O_SMEM_BYTES>>>(w1, w2, out);
}

// round 7
// speedup vs baseline: 1.2481x; 1.2481x over previous
#include <cuda_runtime.h>
#include <math.h>

#define NB 4
#define TDIM 8
#define LP1 197
#define HH 12
#define DD 64
#define CC 768
#define LL 196
#define NT 28   // NB*(TDIM-1)

typedef unsigned long long u64;

__device__ __forceinline__ u64 pk2(float lo, float hi) {
    u64 r; asm("mov.b64 %0,{%1,%2};" : "=l"(r) : "f"(lo), "f"(hi)); return r;
}
__device__ __forceinline__ void upk2(u64 v, float& lo, float& hi) {
    asm("mov.b64 {%0,%1},%2;" : "=f"(lo), "=f"(hi) : "l"(v));
}
__device__ __forceinline__ u64 ffma2(u64 a, u64 b, u64 c) {
    u64 d; asm("fma.rn.f32x2 %0,%1,%2,%3;" : "=l"(d) : "l"(a), "l"(b), "l"(c)); return d;
}
__device__ __forceinline__ u64 fadd2(u64 a, u64 b) {
    u64 d; asm("add.rn.f32x2 %0,%1,%2;" : "=l"(d) : "l"(a), "l"(b)); return d;
}
__device__ __forceinline__ void red2(float* p, float a, float b) {
    asm volatile("red.global.add.v2.f32 [%0], {%1,%2};" :: "l"(p), "f"(a), "f"(b) : "memory");
}

// Scratch: head-averaged attention probabilities for each half.
__device__ float g_P1[NT * LL * LL];
__device__ float g_P2[NT * LL * LL];

// ---------------------------------------------------------------------------
// Kernel 0: zero P scratch and the cls (q=0) rows of out.
// ---------------------------------------------------------------------------
__global__ void zero_kernel(float* __restrict__ out) {
    size_t stride = (size_t)gridDim.x * blockDim.x;
    size_t i = (size_t)blockIdx.x * blockDim.x + threadIdx.x;
    const size_t np = (size_t)NT * LL * LL;
    for (size_t j = i; j < np; j += stride) { g_P1[j] = 0.f; g_P2[j] = 0.f; }
    const size_t ncls = (size_t)NB * TDIM * CC;
    for (size_t j = i; j < ncls; j += stride) {
        size_t nt = j / CC, c = j - nt * CC;
        out[(nt * LP1) * CC + c] = 0.f;
    }
}

// ---------------------------------------------------------------------------
// Kernel 1: attention — EXACT ROUND-4 VERSION (best known: preserves K-tile
// reuse across 196 q rows; R6's per-head small-tile variant regressed 7x on
// K staging traffic).
// ---------------------------------------------------------------------------
#define KS_STRIDE 210
#define QS_STRIDE 65
#define A_SMEM_BYTES ((64*KS_STRIDE + 64*QS_STRIDE) * 4)

__global__ __launch_bounds__(256, 3)
void attn_kernel(const float* __restrict__ q, const float* __restrict__ k) {
    extern __shared__ float sm[];
    float* ks = sm;                          // [64][210]
    float* qs = ks + 64 * KS_STRIDE;         // [64][65]

    int h    = blockIdx.x;
    int nt   = blockIdx.y;
    int half = blockIdx.z >> 1;
    int qh   = blockIdx.z & 1;
    int n = nt / 7, t = nt - n * 7;
    int tq = (half == 0) ? t + 1 : t;
    int tk = (half == 0) ? t : t + 1;

    const float* qb = q + ((size_t)(n * TDIM + tq) * LP1 + 1) * (HH * DD) + h * DD;
    const float* kb = k + ((size_t)(n * TDIM + tk) * LP1 + 1) * (HH * DD) + h * DD;
    float* P = ((half == 0) ? g_P1 : g_P2) + (size_t)nt * LL * LL;

    int tid = threadIdx.x;

    for (int i = tid; i < LL * DD; i += 256) {
        int kk = i >> 6, d = i & 63;
        ks[d * KS_STRIDE + kk] = kb[(size_t)kk * (HH * DD) + d];
    }

    int tx = tid & 15, ty = tid >> 4;

    for (int chunk = 0; chunk < 2; chunk++) {
        int q0 = qh * 98 + chunk * 49;
        __syncthreads();

        for (int i = tid; i < 49 * DD; i += 256) {
            int qq = i >> 6, d = i & 63;
            qs[d * QS_STRIDE + qq] = qb[(size_t)(q0 + qq) * (HH * DD) + d] * 0.125f;
        }
        __syncthreads();

        u64 acc[4][7];
        #pragma unroll
        for (int a = 0; a < 4; a++)
            #pragma unroll
            for (int b = 0; b < 7; b++) acc[a][b] = 0ULL;

        #pragma unroll 4
        for (int d = 0; d < 64; d++) {
            u64 ad[4], bv[7];
            #pragma unroll
            for (int a = 0; a < 4; a++) {
                float av = qs[d * QS_STRIDE + ty + 16 * a];
                ad[a] = pk2(av, av);
            }
            #pragma unroll
            for (int b = 0; b < 7; b++)
                bv[b] = *(const u64*)&ks[d * KS_STRIDE + 2 * tx + 32 * b];
            #pragma unroll
            for (int a = 0; a < 4; a++)
                #pragma unroll
                for (int b = 0; b < 7; b++)
                    acc[a][b] = ffma2(ad[a], bv[b], acc[a][b]);
        }

        #pragma unroll
        for (int a = 0; a < 4; a++) {
            int r = ty + 16 * a;
            float e[14];
            #pragma unroll
            for (int b = 0; b < 7; b++) upk2(acc[a][b], e[2 * b], e[2 * b + 1]);

            bool v6 = (tx < 2);
            float mx = -1e30f;
            #pragma unroll
            for (int b = 0; b < 6; b++) mx = fmaxf(mx, fmaxf(e[2 * b], e[2 * b + 1]));
            if (v6) mx = fmaxf(mx, fmaxf(e[12], e[13]));
            #pragma unroll
            for (int off = 8; off > 0; off >>= 1)
                mx = fmaxf(mx, __shfl_xor_sync(0xffffffffu, mx, off));

            float s = 0.f;
            #pragma unroll
            for (int b = 0; b < 6; b++) {
                e[2 * b]     = __expf(e[2 * b] - mx);
                e[2 * b + 1] = __expf(e[2 * b + 1] - mx);
                s += e[2 * b] + e[2 * b + 1];
            }
            if (v6) {
                e[12] = __expf(e[12] - mx);
                e[13] = __expf(e[13] - mx);
                s += e[12] + e[13];
            }
            #pragma unroll
            for (int off = 8; off > 0; off >>= 1)
                s += __shfl_xor_sync(0xffffffffu, s, off);

            float inv = (1.f / 12.f) / s;
            if (r < 49) {
                float* Pr = P + (size_t)(q0 + r) * LL + 2 * tx;
                #pragma unroll
                for (int b = 0; b < 6; b++)
                    red2(Pr + 32 * b, e[2 * b] * inv, e[2 * b + 1] * inv);
                if (v6) red2(Pr + 192, e[12] * inv, e[13] * inv);
            }
        }
    }
}

// ---------------------------------------------------------------------------
// Kernel 2 (fused halves): out[n,tt,q+1,c] = sum_k P1[n,tt-1,q,k]*w1[IDX[q,k],c]
//                                          + sum_k P2[n,tt  ,q,k]*w2[IDX[q,k],c]
// Block = (c-tile 64, q, n-pair).  256 threads, 4 CTAs/SM (same occ as R4).
// NEW warp partition: sub = lane>>4 (t-half: tt 4sub..4sub+3),
//                     cl  = lane&15 (4 consecutive columns).
// Per k: 1 LDS.128 wv (2 wf, half-warp broadcast) + 1 LDS.128 pp (1 wf)
// for 8 FFMA2 — 3 wavefronts vs round-4's 6, with UNCHANGED acc count (8).
// Subs own disjoint t outputs -> no extra reduction vs round 4.
// ---------------------------------------------------------------------------
#define TCo 64
#define WS_FLOATS (98 * TCo)            // 6272
#define PS_FLOATS (2 * LL * 8)          // 3136 per half
#define O_SMEM_BYTES ((WS_FLOATS + 2 * PS_FLOATS) * 4)   // 50176 B

__global__ __launch_bounds__(256, 4)
void out_kernel(const float* __restrict__ w1, const float* __restrict__ w2,
                float* __restrict__ out) {
    extern __shared__ float sm[];
    float* ws  = sm;                    // [98][64]
    float* psA = sm + WS_FLOATS;        // [2][196*8]  slot tt = P1[t=tt-1], slot0=0
    float* psB = psA + PS_FLOATS;       // [2][196*8]  slot tt = P2[tt],    slot7=0

    int qq = blockIdx.y;
    int c0 = blockIdx.x * TCo;
    int np = blockIdx.z;
    int tid = threadIdx.x;
    int pi = qq / 14, pj = qq - pi * 14;

    // Stage P rows t-strided (both halves, both local n).
    #pragma unroll
    for (int r = 0; r < 14; r++) {
        int n_l = r / 7, t = r - n_l * 7;
        if (tid < LL) {
            int n = np * 2 + n_l;
            size_t base = ((size_t)(n * 7 + t) * LL + qq) * LL + tid;
            psA[n_l * (LL * 8) + tid * 8 + t + 1] = g_P1[base];
            psB[n_l * (LL * 8) + tid * 8 + t]     = g_P2[base];
        }
    }
    if (tid < LL) {
        psA[tid * 8] = 0.f;            psA[LL * 8 + tid * 8] = 0.f;
        psB[tid * 8 + 7] = 0.f;        psB[LL * 8 + tid * 8 + 7] = 0.f;
    }

    int wid = tid >> 5, lane = tid & 31;
    int n_l = wid >> 2, kq = wid & 3;
    int sub = lane >> 4, cl = lane & 15;
    // k slices of 98: 25,25,24,24
    int kst = kq * 25 - ((kq > 2) ? (kq - 2) : 0);
    int kcn = 25 - (kq >= 2 ? 1 : 0);

    u64 acc[8];   // acc[c*2 + tp]: column cl*4+c, t-pair (4sub+2tp, 4sub+2tp+1)
    #pragma unroll
    for (int i = 0; i < 8; i++) acc[i] = 0ULL;

    #pragma unroll
    for (int ph = 0; ph < 4; ph++) {
        const float* w = (ph < 2) ? w1 : w2;
        const float* ps = ((ph < 2) ? psA : psB) + n_l * (LL * 8);
        int kbase = (ph & 1) * 98;

        __syncthreads();   // ws free to overwrite (and ps staged, for ph=0)
        for (int i = tid; i < 98 * 16; i += 256) {
            int kk = i >> 4, cq = i & 15;
            int kg = kbase + kk;
            int ki = kg / 14, kj = kg - ki * 14;
            int idx = (pi - ki + 13) * 27 + (pj - kj + 13);
            *(float4*)&ws[kk * TCo + cq * 4] =
                *(const float4*)(w + (size_t)idx * CC + c0 + cq * 4);
        }
        __syncthreads();

        #pragma unroll 5
        for (int kl = kst; kl < kst + kcn; kl++) {
            float4 wv = *(const float4*)&ws[kl * TCo + cl * 4];
            ulonglong2 pp = *(const ulonglong2*)&ps[(kbase + kl) * 8 + sub * 4];
            u64 b0 = pk2(wv.x, wv.x), b1 = pk2(wv.y, wv.y);
            u64 b2 = pk2(wv.z, wv.z), b3 = pk2(wv.w, wv.w);
            acc[0] = ffma2(pp.x, b0, acc[0]);  acc[1] = ffma2(pp.y, b0, acc[1]);
            acc[2] = ffma2(pp.x, b1, acc[2]);  acc[3] = ffma2(pp.y, b1, acc[3]);
            acc[4] = ffma2(pp.x, b2, acc[4]);  acc[5] = ffma2(pp.y, b2, acc[5]);
            acc[6] = ffma2(pp.x, b3, acc[6]);  acc[7] = ffma2(pp.y, b3, acc[7]);
        }
    }

    // Cross-kq reduction through smem (reuse ws area).  Subs are independent.
    __syncthreads();   // everyone done reading ws
    u64* red = (u64*)ws;
    if (kq) {
        int base = ((n_l * 3 + (kq - 1)) * 32 + lane) * 8;
        #pragma unroll
        for (int j = 0; j < 8; j++) red[base + j] = acc[j];
    }
    __syncthreads();

    if (kq == 0) {
        #pragma unroll
        for (int ww = 0; ww < 3; ww++) {
            int base = ((n_l * 3 + ww) * 32 + lane) * 8;
            #pragma unroll
            for (int j = 0; j < 8; j++) acc[j] = fadd2(acc[j], red[base + j]);
        }
        int n = np * 2 + n_l;
        float a[16];
        #pragma unroll
        for (int i = 0; i < 8; i++) upk2(acc[i], a[2 * i], a[2 * i + 1]);
        #pragma unroll
        for (int tl = 0; tl < 4; tl++) {
            int tt = sub * 4 + tl;
            int tp = tl >> 1, hi = tl & 1;
            float4 o4;
            o4.x = a[(0 * 2 + tp) * 2 + hi];
            o4.y = a[(1 * 2 + tp) * 2 + hi];
            o4.z = a[(2 * 2 + tp) * 2 + hi];
            o4.w = a[(3 * 2 + tp) * 2 + hi];
            *(float4*)(out + ((size_t)(n * TDIM + tt) * LP1 + qq + 1) * CC
                       + c0 + cl * 4) = o4;
        }
    }
}

// ---------------------------------------------------------------------------
extern "C" void kernel_launch(void* const* d_in, const int* in_sizes, int n_in,
                              void* d_out, int out_size) {
    const float* q  = (const float*)d_in[0];
    const float* k  = (const float*)d_in[1];
    const float* w1 = (const float*)d_in[2];
    const float* w2 = (const float*)d_in[3];
    float* out = (float*)d_out;

    cudaFuncSetAttribute(attn_kernel, cudaFuncAttributeMaxDynamicSharedMemorySize, A_SMEM_BYTES);
    cudaFuncSetAttribute(out_kernel,  cudaFuncAttributeMaxDynamicSharedMemorySize, O_SMEM_BYTES);

    zero_kernel<<<512, 256>>>(out);
    attn_kernel<<<dim3(HH, NT, 4), 256, A_SMEM_BYTES>>>(q, k);
    out_kernel<<<dim3(CC / TCo, LL, NB / 2), 256, O_SMEM_BYTES>>>(w1, w2, out);
}

// round 8
// speedup vs baseline: 1.3345x; 1.0693x over previous
#include <cuda_runtime.h>
#include <math.h>

#define NB 4
#define TDIM 8
#define LP1 197
#define HH 12
#define DD 64
#define CC 768
#define LL 196
#define NT 28   // NB*(TDIM-1)

typedef unsigned long long u64;

__device__ __forceinline__ u64 pk2(float lo, float hi) {
    u64 r; asm("mov.b64 %0,{%1,%2};" : "=l"(r) : "f"(lo), "f"(hi)); return r;
}
__device__ __forceinline__ void upk2(u64 v, float& lo, float& hi) {
    asm("mov.b64 {%0,%1},%2;" : "=f"(lo), "=f"(hi) : "l"(v));
}
__device__ __forceinline__ u64 ffma2(u64 a, u64 b, u64 c) {
    u64 d; asm("fma.rn.f32x2 %0,%1,%2,%3;" : "=l"(d) : "l"(a), "l"(b), "l"(c)); return d;
}
__device__ __forceinline__ u64 fadd2(u64 a, u64 b) {
    u64 d; asm("add.rn.f32x2 %0,%1,%2;" : "=l"(d) : "l"(a), "l"(b)); return d;
}
__device__ __forceinline__ void red2(float* p, float a, float b) {
    asm volatile("red.global.add.v2.f32 [%0], {%1,%2};" :: "l"(p), "f"(a), "f"(b) : "memory");
}

// Scratch: head-averaged attention probabilities for each half.
__device__ float g_P1[NT * LL * LL];
__device__ float g_P2[NT * LL * LL];

// ---------------------------------------------------------------------------
// Kernel 0: zero P scratch and the cls (q=0) rows of out.
// ---------------------------------------------------------------------------
__global__ void zero_kernel(float* __restrict__ out) {
    size_t stride = (size_t)gridDim.x * blockDim.x;
    size_t i = (size_t)blockIdx.x * blockDim.x + threadIdx.x;
    const size_t np = (size_t)NT * LL * LL;
    for (size_t j = i; j < np; j += stride) { g_P1[j] = 0.f; g_P2[j] = 0.f; }
    const size_t ncls = (size_t)NB * TDIM * CC;
    for (size_t j = i; j < ncls; j += stride) {
        size_t nt = j / CC, c = j - nt * CC;
        out[(nt * LP1) * CC + c] = 0.f;
    }
}

// ---------------------------------------------------------------------------
// Kernel 1: attention — EXACT ROUND-4 VERSION (protected; at its issue ceiling
// given 67% useful-lane efficiency).
// ---------------------------------------------------------------------------
#define KS_STRIDE 210
#define QS_STRIDE 65
#define A_SMEM_BYTES ((64*KS_STRIDE + 64*QS_STRIDE) * 4)

__global__ __launch_bounds__(256, 3)
void attn_kernel(const float* __restrict__ q, const float* __restrict__ k) {
    extern __shared__ float sm[];
    float* ks = sm;                          // [64][210]
    float* qs = ks + 64 * KS_STRIDE;         // [64][65]

    int h    = blockIdx.x;
    int nt   = blockIdx.y;
    int half = blockIdx.z >> 1;
    int qh   = blockIdx.z & 1;
    int n = nt / 7, t = nt - n * 7;
    int tq = (half == 0) ? t + 1 : t;
    int tk = (half == 0) ? t : t + 1;

    const float* qb = q + ((size_t)(n * TDIM + tq) * LP1 + 1) * (HH * DD) + h * DD;
    const float* kb = k + ((size_t)(n * TDIM + tk) * LP1 + 1) * (HH * DD) + h * DD;
    float* P = ((half == 0) ? g_P1 : g_P2) + (size_t)nt * LL * LL;

    int tid = threadIdx.x;

    for (int i = tid; i < LL * DD; i += 256) {
        int kk = i >> 6, d = i & 63;
        ks[d * KS_STRIDE + kk] = kb[(size_t)kk * (HH * DD) + d];
    }

    int tx = tid & 15, ty = tid >> 4;

    for (int chunk = 0; chunk < 2; chunk++) {
        int q0 = qh * 98 + chunk * 49;
        __syncthreads();

        for (int i = tid; i < 49 * DD; i += 256) {
            int qq = i >> 6, d = i & 63;
            qs[d * QS_STRIDE + qq] = qb[(size_t)(q0 + qq) * (HH * DD) + d] * 0.125f;
        }
        __syncthreads();

        u64 acc[4][7];
        #pragma unroll
        for (int a = 0; a < 4; a++)
            #pragma unroll
            for (int b = 0; b < 7; b++) acc[a][b] = 0ULL;

        #pragma unroll 4
        for (int d = 0; d < 64; d++) {
            u64 ad[4], bv[7];
            #pragma unroll
            for (int a = 0; a < 4; a++) {
                float av = qs[d * QS_STRIDE + ty + 16 * a];
                ad[a] = pk2(av, av);
            }
            #pragma unroll
            for (int b = 0; b < 7; b++)
                bv[b] = *(const u64*)&ks[d * KS_STRIDE + 2 * tx + 32 * b];
            #pragma unroll
            for (int a = 0; a < 4; a++)
                #pragma unroll
                for (int b = 0; b < 7; b++)
                    acc[a][b] = ffma2(ad[a], bv[b], acc[a][b]);
        }

        #pragma unroll
        for (int a = 0; a < 4; a++) {
            int r = ty + 16 * a;
            float e[14];
            #pragma unroll
            for (int b = 0; b < 7; b++) upk2(acc[a][b], e[2 * b], e[2 * b + 1]);

            bool v6 = (tx < 2);
            float mx = -1e30f;
            #pragma unroll
            for (int b = 0; b < 6; b++) mx = fmaxf(mx, fmaxf(e[2 * b], e[2 * b + 1]));
            if (v6) mx = fmaxf(mx, fmaxf(e[12], e[13]));
            #pragma unroll
            for (int off = 8; off > 0; off >>= 1)
                mx = fmaxf(mx, __shfl_xor_sync(0xffffffffu, mx, off));

            float s = 0.f;
            #pragma unroll
            for (int b = 0; b < 6; b++) {
                e[2 * b]     = __expf(e[2 * b] - mx);
                e[2 * b + 1] = __expf(e[2 * b + 1] - mx);
                s += e[2 * b] + e[2 * b + 1];
            }
            if (v6) {
                e[12] = __expf(e[12] - mx);
                e[13] = __expf(e[13] - mx);
                s += e[12] + e[13];
            }
            #pragma unroll
            for (int off = 8; off > 0; off >>= 1)
                s += __shfl_xor_sync(0xffffffffu, s, off);

            float inv = (1.f / 12.f) / s;
            if (r < 49) {
                float* Pr = P + (size_t)(q0 + r) * LL + 2 * tx;
                #pragma unroll
                for (int b = 0; b < 6; b++)
                    red2(Pr + 32 * b, e[2 * b] * inv, e[2 * b + 1] * inv);
                if (v6) red2(Pr + 192, e[12] * inv, e[13] * inv);
            }
        }
    }
}

// ---------------------------------------------------------------------------
// Kernel 2 (fused halves, np-MERGED): one block = (c-tile 64, q) for ALL 4 n.
// out[n,tt,q+1,c] = sum_k P1[n,tt-1,q,k]*w1[IDX[q,k],c]
//                 + sum_k P2[n,tt  ,q,k]*w2[IDX[q,k],c]
// 256 threads, 3 CTAs/SM (75.3KB smem).  8 warps = 4 n x 2 k-halves.
// w-gather L2 traffic HALVED vs np=2 (each (c-tile,q) gathered once, serves 4 n).
// Warp lanes: sub = lane>>4 (t-half), cl = lane&15 (4 consecutive cols).
// ---------------------------------------------------------------------------
#define TCo 64
#define WS_FLOATS (98 * TCo)            // 6272
#define PS_FLOATS (4 * LL * 8)          // 6272 per half (4 n)
#define O_SMEM_BYTES ((WS_FLOATS + 2 * PS_FLOATS) * 4)   // 75264 B

__global__ __launch_bounds__(256, 3)
void out_kernel(const float* __restrict__ w1, const float* __restrict__ w2,
                float* __restrict__ out) {
    extern __shared__ float sm[];
    float* ws  = sm;                    // [98][64]
    float* psA = sm + WS_FLOATS;        // [4][196*8]  slot tt = P1[t=tt-1], slot0=0
    float* psB = psA + PS_FLOATS;       // [4][196*8]  slot tt = P2[tt],    slot7=0

    int qq = blockIdx.y;
    int c0 = blockIdx.x * TCo;
    int tid = threadIdx.x;
    int pi = qq / 14, pj = qq - pi * 14;

    // Stage P rows t-strided for all 4 n, both halves.
    #pragma unroll
    for (int r = 0; r < 28; r++) {
        int n_l = r / 7, t = r - n_l * 7;
        if (tid < LL) {
            size_t base = ((size_t)(n_l * 7 + t) * LL + qq) * LL + tid;
            psA[n_l * (LL * 8) + tid * 8 + t + 1] = g_P1[base];
            psB[n_l * (LL * 8) + tid * 8 + t]     = g_P2[base];
        }
    }
    if (tid < LL) {
        #pragma unroll
        for (int n_l = 0; n_l < 4; n_l++) {
            psA[n_l * (LL * 8) + tid * 8] = 0.f;
            psB[n_l * (LL * 8) + tid * 8 + 7] = 0.f;
        }
    }

    int wid = tid >> 5, lane = tid & 31;
    int n_l = wid >> 1, kq = wid & 1;
    int sub = lane >> 4, cl = lane & 15;
    int kst = kq * 49;                  // k-half within each 98-row w tile

    u64 acc[8];   // acc[c*2 + tp]: column cl*4+c, t-pair (4sub+2tp, 4sub+2tp+1)
    #pragma unroll
    for (int i = 0; i < 8; i++) acc[i] = 0ULL;

    #pragma unroll
    for (int ph = 0; ph < 4; ph++) {
        const float* w = (ph < 2) ? w1 : w2;
        const float* ps = ((ph < 2) ? psA : psB) + n_l * (LL * 8);
        int kbase = (ph & 1) * 98;

        __syncthreads();   // ws free to overwrite (and ps staged, for ph=0)
        for (int i = tid; i < 98 * 16; i += 256) {
            int kk = i >> 4, cq = i & 15;
            int kg = kbase + kk;
            int ki = kg / 14, kj = kg - ki * 14;
            int idx = (pi - ki + 13) * 27 + (pj - kj + 13);
            *(float4*)&ws[kk * TCo + cq * 4] =
                *(const float4*)(w + (size_t)idx * CC + c0 + cq * 4);
        }
        __syncthreads();

        #pragma unroll 7
        for (int kl = kst; kl < kst + 49; kl++) {
            float4 wv = *(const float4*)&ws[kl * TCo + cl * 4];
            ulonglong2 pp = *(const ulonglong2*)&ps[(kbase + kl) * 8 + sub * 4];
            u64 b0 = pk2(wv.x, wv.x), b1 = pk2(wv.y, wv.y);
            u64 b2 = pk2(wv.z, wv.z), b3 = pk2(wv.w, wv.w);
            acc[0] = ffma2(pp.x, b0, acc[0]);  acc[1] = ffma2(pp.y, b0, acc[1]);
            acc[2] = ffma2(pp.x, b1, acc[2]);  acc[3] = ffma2(pp.y, b1, acc[3]);
            acc[4] = ffma2(pp.x, b2, acc[4]);  acc[5] = ffma2(pp.y, b2, acc[5]);
            acc[6] = ffma2(pp.x, b3, acc[6]);  acc[7] = ffma2(pp.y, b3, acc[7]);
        }
    }

    // Cross-k-half reduction through smem (reuse ws area).  Subs independent.
    __syncthreads();   // everyone done reading ws
    u64* red = (u64*)ws;
    if (kq) {
        int base = (n_l * 32 + lane) * 8;
        #pragma unroll
        for (int j = 0; j < 8; j++) red[base + j] = acc[j];
    }
    __syncthreads();

    if (kq == 0) {
        int base = (n_l * 32 + lane) * 8;
        #pragma unroll
        for (int j = 0; j < 8; j++) acc[j] = fadd2(acc[j], red[base + j]);

        float a[16];
        #pragma unroll
        for (int i = 0; i < 8; i++) upk2(acc[i], a[2 * i], a[2 * i + 1]);
        #pragma unroll
        for (int tl = 0; tl < 4; tl++) {
            int tt = sub * 4 + tl;
            int tp = tl >> 1, hi = tl & 1;
            float4 o4;
            o4.x = a[(0 * 2 + tp) * 2 + hi];
            o4.y = a[(1 * 2 + tp) * 2 + hi];
            o4.z = a[(2 * 2 + tp) * 2 + hi];
            o4.w = a[(3 * 2 + tp) * 2 + hi];
            *(float4*)(out + ((size_t)(n_l * TDIM + tt) * LP1 + qq + 1) * CC
                       + c0 + cl * 4) = o4;
        }
    }
}

// ---------------------------------------------------------------------------
extern "C" void kernel_launch(void* const* d_in, const int* in_sizes, int n_in,
                              void* d_out, int out_size) {
    const float* q  = (const float*)d_in[0];
    const float* k  = (const float*)d_in[1];
    const float* w1 = (const float*)d_in[2];
    const float* w2 = (const float*)d_in[3];
    float* out = (float*)d_out;

    cudaFuncSetAttribute(attn_kernel, cudaFuncAttributeMaxDynamicSharedMemorySize, A_SMEM_BYTES);
    cudaFuncSetAttribute(out_kernel,  cudaFuncAttributeMaxDynamicSharedMemorySize, O_SMEM_BYTES);

    zero_kernel<<<512, 256>>>(out);
    attn_kernel<<<dim3(HH, NT, 4), 256, A_SMEM_BYTES>>>(q, k);
    out_kernel<<<dim3(CC / TCo, LL, 1), 256, O_SMEM_BYTES>>>(w1, w2, out);
}

// round 9
// speedup vs baseline: 1.3693x; 1.0260x over previous
#include <cuda_runtime.h>
#include <math.h>

#define NB 4
#define TDIM 8
#define LP1 197
#define HH 12
#define DD 64
#define CC 768
#define LL 196
#define NT 28   // NB*(TDIM-1)

typedef unsigned long long u64;

__device__ __forceinline__ u64 pk2(float lo, float hi) {
    u64 r; asm("mov.b64 %0,{%1,%2};" : "=l"(r) : "f"(lo), "f"(hi)); return r;
}
__device__ __forceinline__ void upk2(u64 v, float& lo, float& hi) {
    asm("mov.b64 {%0,%1},%2;" : "=f"(lo), "=f"(hi) : "l"(v));
}
__device__ __forceinline__ u64 ffma2(u64 a, u64 b, u64 c) {
    u64 d; asm("fma.rn.f32x2 %0,%1,%2,%3;" : "=l"(d) : "l"(a), "l"(b), "l"(c)); return d;
}
__device__ __forceinline__ u64 fadd2(u64 a, u64 b) {
    u64 d; asm("add.rn.f32x2 %0,%1,%2;" : "=l"(d) : "l"(a), "l"(b)); return d;
}
__device__ __forceinline__ void red2(float* p, float a, float b) {
    asm volatile("red.global.add.v2.f32 [%0], {%1,%2};" :: "l"(p), "f"(a), "f"(b) : "memory");
}

// Scratch: head-averaged attention probabilities for each half.
__device__ float g_P1[NT * LL * LL];
__device__ float g_P2[NT * LL * LL];

// ---------------------------------------------------------------------------
// Kernel 0: zero P scratch and the cls (q=0) rows of out.
// ---------------------------------------------------------------------------
__global__ void zero_kernel(float* __restrict__ out) {
    size_t stride = (size_t)gridDim.x * blockDim.x;
    size_t i = (size_t)blockIdx.x * blockDim.x + threadIdx.x;
    const size_t np = (size_t)NT * LL * LL;
    for (size_t j = i; j < np; j += stride) { g_P1[j] = 0.f; g_P2[j] = 0.f; }
    const size_t ncls = (size_t)NB * TDIM * CC;
    for (size_t j = i; j < ncls; j += stride) {
        size_t nt = j / CC, c = j - nt * CC;
        out[(nt * LP1) * CC + c] = 0.f;
    }
}

// ---------------------------------------------------------------------------
// Kernel 1: attention, z=3 row chunking.  Block = (h, nt, half*3+qh).
// qh 0,1: rows [qh*64, qh*64+64)  — full 64-row chunk, 4 rows/thread, NO waste.
// qh 2:   rows [128,192) main + [192,196) tail via a cheap second pass.
// 256 threads (16x16), 3 CTAs/SM (71.4KB smem).  f32x2 GEMM, register softmax
// per half-warp row, red2 head-mean accumulate into P.
// ---------------------------------------------------------------------------
#define KS_STRIDE 210
#define QS_STRIDE 69
#define A_SMEM_BYTES ((64*KS_STRIDE + 64*QS_STRIDE) * 4)   // 71424 B

__global__ __launch_bounds__(256, 3)
void attn_kernel(const float* __restrict__ q, const float* __restrict__ k) {
    extern __shared__ float sm[];
    float* ks = sm;                          // [64][210]
    float* qs = ks + 64 * KS_STRIDE;         // [64][69]  (up to 68 rows used)

    int h    = blockIdx.x;
    int nt   = blockIdx.y;
    int half = blockIdx.z / 3;
    int qh   = blockIdx.z - half * 3;
    int n = nt / 7, t = nt - n * 7;
    int tq = (half == 0) ? t + 1 : t;
    int tk = (half == 0) ? t : t + 1;
    int q0 = qh * 64;
    int nrows = (qh == 2) ? 68 : 64;

    const float* qb = q + ((size_t)(n * TDIM + tq) * LP1 + 1) * (HH * DD) + h * DD;
    const float* kb = k + ((size_t)(n * TDIM + tk) * LP1 + 1) * (HH * DD) + h * DD;
    float* P = ((half == 0) ? g_P1 : g_P2) + (size_t)nt * LL * LL;

    int tid = threadIdx.x;

    // K tile transposed: ks[d][kk] = k[kk][d]
    for (int i = tid; i < LL * DD; i += 256) {
        int kk = i >> 6, d = i & 63;
        ks[d * KS_STRIDE + kk] = kb[(size_t)kk * (HH * DD) + d];
    }
    // Q rows transposed, pre-scaled
    for (int i = tid; i < nrows * DD; i += 256) {
        int qq = i >> 6, d = i & 63;
        qs[d * QS_STRIDE + qq] = qb[(size_t)(q0 + qq) * (HH * DD) + d] * 0.125f;
    }
    __syncthreads();

    int tx = tid & 15, ty = tid >> 4;

    // Main 64x196 GEMM over K=64: 4 rows x 7 col-pairs per thread, all valid.
    u64 acc[4][7];
    #pragma unroll
    for (int a = 0; a < 4; a++)
        #pragma unroll
        for (int b = 0; b < 7; b++) acc[a][b] = 0ULL;

    #pragma unroll 4
    for (int d = 0; d < 64; d++) {
        u64 ad[4], bv[7];
        #pragma unroll
        for (int a = 0; a < 4; a++) {
            float av = qs[d * QS_STRIDE + ty + 16 * a];
            ad[a] = pk2(av, av);
        }
        #pragma unroll
        for (int b = 0; b < 7; b++)
            bv[b] = *(const u64*)&ks[d * KS_STRIDE + 2 * tx + 32 * b];
        #pragma unroll
        for (int a = 0; a < 4; a++)
            #pragma unroll
            for (int b = 0; b < 7; b++)
                acc[a][b] = ffma2(ad[a], bv[b], acc[a][b]);
    }

    // Register softmax per row (half-warp owns a row); no row guards.
    #pragma unroll
    for (int a = 0; a < 4; a++) {
        float e[14];
        #pragma unroll
        for (int b = 0; b < 7; b++) upk2(acc[a][b], e[2 * b], e[2 * b + 1]);

        bool v6 = (tx < 2);
        float mx = -1e30f;
        #pragma unroll
        for (int b = 0; b < 6; b++) mx = fmaxf(mx, fmaxf(e[2 * b], e[2 * b + 1]));
        if (v6) mx = fmaxf(mx, fmaxf(e[12], e[13]));
        #pragma unroll
        for (int off = 8; off > 0; off >>= 1)
            mx = fmaxf(mx, __shfl_xor_sync(0xffffffffu, mx, off));

        float s = 0.f;
        #pragma unroll
        for (int b = 0; b < 6; b++) {
            e[2 * b]     = __expf(e[2 * b] - mx);
            e[2 * b + 1] = __expf(e[2 * b + 1] - mx);
            s += e[2 * b] + e[2 * b + 1];
        }
        if (v6) {
            e[12] = __expf(e[12] - mx);
            e[13] = __expf(e[13] - mx);
            s += e[12] + e[13];
        }
        #pragma unroll
        for (int off = 8; off > 0; off >>= 1)
            s += __shfl_xor_sync(0xffffffffu, s, off);

        float inv = (1.f / 12.f) / s;
        float* Pr = P + (size_t)(q0 + ty + 16 * a) * LL + 2 * tx;
        #pragma unroll
        for (int b = 0; b < 6; b++)
            red2(Pr + 32 * b, e[2 * b] * inv, e[2 * b + 1] * inv);
        if (v6) red2(Pr + 192, e[12] * inv, e[13] * inv);
    }

    // Global 4-row tail (rows 192..195), qh==2 blocks only.  Second 64-d pass;
    // acc registers are dead after the main softmax, so no pressure increase.
    if (qh == 2) {
        int qq2 = 64 + (ty & 3);       // staged (68 rows); ty>=4 duplicates, discarded
        u64 acct[7];
        #pragma unroll
        for (int b = 0; b < 7; b++) acct[b] = 0ULL;

        #pragma unroll 4
        for (int d = 0; d < 64; d++) {
            float av = qs[d * QS_STRIDE + qq2];
            u64 ad = pk2(av, av);
            #pragma unroll
            for (int b = 0; b < 7; b++)
                acct[b] = ffma2(ad, *(const u64*)&ks[d * KS_STRIDE + 2 * tx + 32 * b], acct[b]);
        }

        float e[14];
        #pragma unroll
        for (int b = 0; b < 7; b++) upk2(acct[b], e[2 * b], e[2 * b + 1]);

        bool v6 = (tx < 2);
        float mx = -1e30f;
        #pragma unroll
        for (int b = 0; b < 6; b++) mx = fmaxf(mx, fmaxf(e[2 * b], e[2 * b + 1]));
        if (v6) mx = fmaxf(mx, fmaxf(e[12], e[13]));
        #pragma unroll
        for (int off = 8; off > 0; off >>= 1)
            mx = fmaxf(mx, __shfl_xor_sync(0xffffffffu, mx, off));

        float s = 0.f;
        #pragma unroll
        for (int b = 0; b < 6; b++) {
            e[2 * b]     = __expf(e[2 * b] - mx);
            e[2 * b + 1] = __expf(e[2 * b + 1] - mx);
            s += e[2 * b] + e[2 * b + 1];
        }
        if (v6) {
            e[12] = __expf(e[12] - mx);
            e[13] = __expf(e[13] - mx);
            s += e[12] + e[13];
        }
        #pragma unroll
        for (int off = 8; off > 0; off >>= 1)
            s += __shfl_xor_sync(0xffffffffu, s, off);

        float inv = (1.f / 12.f) / s;
        if (ty < 4) {
            float* Pr = P + (size_t)(192 + ty) * LL + 2 * tx;
            #pragma unroll
            for (int b = 0; b < 6; b++)
                red2(Pr + 32 * b, e[2 * b] * inv, e[2 * b + 1] * inv);
            if (v6) red2(Pr + 192, e[12] * inv, e[13] * inv);
        }
    }
}

// ---------------------------------------------------------------------------
// Kernel 2 (fused halves, np-merged) — EXACT ROUND-8 VERSION (protected win).
// ---------------------------------------------------------------------------
#define TCo 64
#define WS_FLOATS (98 * TCo)            // 6272
#define PS_FLOATS (4 * LL * 8)          // 6272 per half (4 n)
#define O_SMEM_BYTES ((WS_FLOATS + 2 * PS_FLOATS) * 4)   // 75264 B

__global__ __launch_bounds__(256, 3)
void out_kernel(const float* __restrict__ w1, const float* __restrict__ w2,
                float* __restrict__ out) {
    extern __shared__ float sm[];
    float* ws  = sm;                    // [98][64]
    float* psA = sm + WS_FLOATS;        // [4][196*8]  slot tt = P1[t=tt-1], slot0=0
    float* psB = psA + PS_FLOATS;       // [4][196*8]  slot tt = P2[tt],    slot7=0

    int qq = blockIdx.y;
    int c0 = blockIdx.x * TCo;
    int tid = threadIdx.x;
    int pi = qq / 14, pj = qq - pi * 14;

    #pragma unroll
    for (int r = 0; r < 28; r++) {
        int n_l = r / 7, t = r - n_l * 7;
        if (tid < LL) {
            size_t base = ((size_t)(n_l * 7 + t) * LL + qq) * LL + tid;
            psA[n_l * (LL * 8) + tid * 8 + t + 1] = g_P1[base];
            psB[n_l * (LL * 8) + tid * 8 + t]     = g_P2[base];
        }
    }
    if (tid < LL) {
        #pragma unroll
        for (int n_l = 0; n_l < 4; n_l++) {
            psA[n_l * (LL * 8) + tid * 8] = 0.f;
            psB[n_l * (LL * 8) + tid * 8 + 7] = 0.f;
        }
    }

    int wid = tid >> 5, lane = tid & 31;
    int n_l = wid >> 1, kq = wid & 1;
    int sub = lane >> 4, cl = lane & 15;
    int kst = kq * 49;

    u64 acc[8];
    #pragma unroll
    for (int i = 0; i < 8; i++) acc[i] = 0ULL;

    #pragma unroll
    for (int ph = 0; ph < 4; ph++) {
        const float* w = (ph < 2) ? w1 : w2;
        const float* ps = ((ph < 2) ? psA : psB) + n_l * (LL * 8);
        int kbase = (ph & 1) * 98;

        __syncthreads();
        for (int i = tid; i < 98 * 16; i += 256) {
            int kk = i >> 4, cq = i & 15;
            int kg = kbase + kk;
            int ki = kg / 14, kj = kg - ki * 14;
            int idx = (pi - ki + 13) * 27 + (pj - kj + 13);
            *(float4*)&ws[kk * TCo + cq * 4] =
                *(const float4*)(w + (size_t)idx * CC + c0 + cq * 4);
        }
        __syncthreads();

        #pragma unroll 7
        for (int kl = kst; kl < kst + 49; kl++) {
            float4 wv = *(const float4*)&ws[kl * TCo + cl * 4];
            ulonglong2 pp = *(const ulonglong2*)&ps[(kbase + kl) * 8 + sub * 4];
            u64 b0 = pk2(wv.x, wv.x), b1 = pk2(wv.y, wv.y);
            u64 b2 = pk2(wv.z, wv.z), b3 = pk2(wv.w, wv.w);
            acc[0] = ffma2(pp.x, b0, acc[0]);  acc[1] = ffma2(pp.y, b0, acc[1]);
            acc[2] = ffma2(pp.x, b1, acc[2]);  acc[3] = ffma2(pp.y, b1, acc[3]);
            acc[4] = ffma2(pp.x, b2, acc[4]);  acc[5] = ffma2(pp.y, b2, acc[5]);
            acc[6] = ffma2(pp.x, b3, acc[6]);  acc[7] = ffma2(pp.y, b3, acc[7]);
        }
    }

    __syncthreads();
    u64* red = (u64*)ws;
    if (kq) {
        int base = (n_l * 32 + lane) * 8;
        #pragma unroll
        for (int j = 0; j < 8; j++) red[base + j] = acc[j];
    }
    __syncthreads();

    if (kq == 0) {
        int base = (n_l * 32 + lane) * 8;
        #pragma unroll
        for (int j = 0; j < 8; j++) acc[j] = fadd2(acc[j], red[base + j]);

        float a[16];
        #pragma unroll
        for (int i = 0; i < 8; i++) upk2(acc[i], a[2 * i], a[2 * i + 1]);
        #pragma unroll
        for (int tl = 0; tl < 4; tl++) {
            int tt = sub * 4 + tl;
            int tp = tl >> 1, hi = tl & 1;
            float4 o4;
            o4.x = a[(0 * 2 + tp) * 2 + hi];
            o4.y = a[(1 * 2 + tp) * 2 + hi];
            o4.z = a[(2 * 2 + tp) * 2 + hi];
            o4.w = a[(3 * 2 + tp) * 2 + hi];
            *(float4*)(out + ((size_t)(n_l * TDIM + tt) * LP1 + qq + 1) * CC
                       + c0 + cl * 4) = o4;
        }
    }
}

// ---------------------------------------------------------------------------
extern "C" void kernel_launch(void* const* d_in, const int* in_sizes, int n_in,
                              void* d_out, int out_size) {
    const float* q  = (const float*)d_in[0];
    const float* k  = (const float*)d_in[1];
    const float* w1 = (const float*)d_in[2];
    const float* w2 = (const float*)d_in[3];
    float* out = (float*)d_out;

    cudaFuncSetAttribute(attn_kernel, cudaFuncAttributeMaxDynamicSharedMemorySize, A_SMEM_BYTES);
    cudaFuncSetAttribute(out_kernel,  cudaFuncAttributeMaxDynamicSharedMemorySize, O_SMEM_BYTES);

    zero_kernel<<<512, 256>>>(out);
    attn_kernel<<<dim3(HH, NT, 6), 256, A_SMEM_BYTES>>>(q, k);
    out_kernel<<<dim3(CC / TCo, LL, 1), 256, O_SMEM_BYTES>>>(w1, w2, out);
}

// round 10
// speedup vs baseline: 1.4178x; 1.0354x over previous
#include <cuda_runtime.h>
#include <math.h>

#define NB 4
#define TDIM 8
#define LP1 197
#define HH 12
#define DD 64
#define CC 768
#define LL 196
#define NT 28   // NB*(TDIM-1)

typedef unsigned long long u64;

__device__ __forceinline__ u64 pk2(float lo, float hi) {
    u64 r; asm("mov.b64 %0,{%1,%2};" : "=l"(r) : "f"(lo), "f"(hi)); return r;
}
__device__ __forceinline__ void upk2(u64 v, float& lo, float& hi) {
    asm("mov.b64 {%0,%1},%2;" : "=f"(lo), "=f"(hi) : "l"(v));
}
__device__ __forceinline__ u64 ffma2(u64 a, u64 b, u64 c) {
    u64 d; asm("fma.rn.f32x2 %0,%1,%2,%3;" : "=l"(d) : "l"(a), "l"(b), "l"(c)); return d;
}
__device__ __forceinline__ u64 fadd2(u64 a, u64 b) {
    u64 d; asm("add.rn.f32x2 %0,%1,%2;" : "=l"(d) : "l"(a), "l"(b)); return d;
}
__device__ __forceinline__ void red4(float* p, float a, float b, float c, float d) {
    asm volatile("red.global.add.v4.f32 [%0], {%1,%2,%3,%4};"
                 :: "l"(p), "f"(a), "f"(b), "f"(c), "f"(d) : "memory");
}

// Scratch: head-averaged attention probabilities for each half.
__device__ float g_P1[NT * LL * LL];
__device__ float g_P2[NT * LL * LL];

// ---------------------------------------------------------------------------
// Kernel 0: zero P scratch and the cls (q=0) rows of out.
// ---------------------------------------------------------------------------
__global__ void zero_kernel(float* __restrict__ out) {
    size_t stride = (size_t)gridDim.x * blockDim.x;
    size_t i = (size_t)blockIdx.x * blockDim.x + threadIdx.x;
    const size_t np = (size_t)NT * LL * LL;
    for (size_t j = i; j < np; j += stride) { g_P1[j] = 0.f; g_P2[j] = 0.f; }
    const size_t ncls = (size_t)NB * TDIM * CC;
    for (size_t j = i; j < ncls; j += stride) {
        size_t nt = j / CC, c = j - nt * CC;
        out[(nt * LP1) * CC + c] = 0.f;
    }
}

// ---------------------------------------------------------------------------
// Kernel 1: attention, z=3 row chunking (round-9 structure).
// CHANGE vs R9: P accumulation now pairs adjacent lanes via one u64 shfl and
// issues red.global.add.v4.f32 from even-tx lanes only — same REDG instruction
// count, HALF the active REDG lanes (tests the REDG per-lane cost model).
// ---------------------------------------------------------------------------
#define KS_STRIDE 210
#define QS_STRIDE 69
#define A_SMEM_BYTES ((64*KS_STRIDE + 64*QS_STRIDE) * 4)   // 71424 B

// Scaled-probability store: pv[b] holds cols (32b+2tx, 32b+2tx+1) of this row.
// Even tx gathers odd neighbor's pair -> one 16B quad -> red4.
__device__ __forceinline__ void store_row_v4(float* Pr, const u64* pv, int tx) {
    #pragma unroll
    for (int b = 0; b < 7; b++) {
        u64 nb = __shfl_down_sync(0xffffffffu, pv[b], 1);
        if ((tx & 1) == 0 && (b < 6 || tx == 0)) {
            float a0, a1, b0, b1;
            upk2(pv[b], a0, a1);
            upk2(nb,    b0, b1);
            red4(Pr + 32 * b + 2 * tx, a0, a1, b0, b1);
        }
    }
}

__global__ __launch_bounds__(256, 3)
void attn_kernel(const float* __restrict__ q, const float* __restrict__ k) {
    extern __shared__ float sm[];
    float* ks = sm;                          // [64][210]
    float* qs = ks + 64 * KS_STRIDE;         // [64][69]  (up to 68 rows used)

    int h    = blockIdx.x;
    int nt   = blockIdx.y;
    int half = blockIdx.z / 3;
    int qh   = blockIdx.z - half * 3;
    int n = nt / 7, t = nt - n * 7;
    int tq = (half == 0) ? t + 1 : t;
    int tk = (half == 0) ? t : t + 1;
    int q0 = qh * 64;
    int nrows = (qh == 2) ? 68 : 64;

    const float* qb = q + ((size_t)(n * TDIM + tq) * LP1 + 1) * (HH * DD) + h * DD;
    const float* kb = k + ((size_t)(n * TDIM + tk) * LP1 + 1) * (HH * DD) + h * DD;
    float* P = ((half == 0) ? g_P1 : g_P2) + (size_t)nt * LL * LL;

    int tid = threadIdx.x;

    // K tile transposed: ks[d][kk] = k[kk][d]
    for (int i = tid; i < LL * DD; i += 256) {
        int kk = i >> 6, d = i & 63;
        ks[d * KS_STRIDE + kk] = kb[(size_t)kk * (HH * DD) + d];
    }
    // Q rows transposed, pre-scaled
    for (int i = tid; i < nrows * DD; i += 256) {
        int qq = i >> 6, d = i & 63;
        qs[d * QS_STRIDE + qq] = qb[(size_t)(q0 + qq) * (HH * DD) + d] * 0.125f;
    }
    __syncthreads();

    int tx = tid & 15, ty = tid >> 4;

    // Main 64x196 GEMM over K=64: 4 rows x 7 col-pairs per thread, all valid.
    u64 acc[4][7];
    #pragma unroll
    for (int a = 0; a < 4; a++)
        #pragma unroll
        for (int b = 0; b < 7; b++) acc[a][b] = 0ULL;

    #pragma unroll 4
    for (int d = 0; d < 64; d++) {
        u64 ad[4], bv[7];
        #pragma unroll
        for (int a = 0; a < 4; a++) {
            float av = qs[d * QS_STRIDE + ty + 16 * a];
            ad[a] = pk2(av, av);
        }
        #pragma unroll
        for (int b = 0; b < 7; b++)
            bv[b] = *(const u64*)&ks[d * KS_STRIDE + 2 * tx + 32 * b];
        #pragma unroll
        for (int a = 0; a < 4; a++)
            #pragma unroll
            for (int b = 0; b < 7; b++)
                acc[a][b] = ffma2(ad[a], bv[b], acc[a][b]);
    }

    // Register softmax per row (half-warp owns a row); no row guards.
    #pragma unroll
    for (int a = 0; a < 4; a++) {
        float e[14];
        #pragma unroll
        for (int b = 0; b < 7; b++) upk2(acc[a][b], e[2 * b], e[2 * b + 1]);

        bool v6 = (tx < 2);
        float mx = -1e30f;
        #pragma unroll
        for (int b = 0; b < 6; b++) mx = fmaxf(mx, fmaxf(e[2 * b], e[2 * b + 1]));
        if (v6) mx = fmaxf(mx, fmaxf(e[12], e[13]));
        #pragma unroll
        for (int off = 8; off > 0; off >>= 1)
            mx = fmaxf(mx, __shfl_xor_sync(0xffffffffu, mx, off));

        float s = 0.f;
        #pragma unroll
        for (int b = 0; b < 6; b++) {
            e[2 * b]     = __expf(e[2 * b] - mx);
            e[2 * b + 1] = __expf(e[2 * b + 1] - mx);
            s += e[2 * b] + e[2 * b + 1];
        }
        if (v6) {
            e[12] = __expf(e[12] - mx);
            e[13] = __expf(e[13] - mx);
            s += e[12] + e[13];
        }
        #pragma unroll
        for (int off = 8; off > 0; off >>= 1)
            s += __shfl_xor_sync(0xffffffffu, s, off);

        float inv = (1.f / 12.f) / s;
        u64 pv[7];
        #pragma unroll
        for (int b = 0; b < 7; b++)
            pv[b] = pk2(e[2 * b] * inv, e[2 * b + 1] * inv);
        store_row_v4(P + (size_t)(q0 + ty + 16 * a) * LL, pv, tx);
    }

    // Global 4-row tail (rows 192..195), qh==2 blocks only.
    if (qh == 2) {
        int qq2 = 64 + (ty & 3);
        u64 acct[7];
        #pragma unroll
        for (int b = 0; b < 7; b++) acct[b] = 0ULL;

        #pragma unroll 4
        for (int d = 0; d < 64; d++) {
            float av = qs[d * QS_STRIDE + qq2];
            u64 ad = pk2(av, av);
            #pragma unroll
            for (int b = 0; b < 7; b++)
                acct[b] = ffma2(ad, *(const u64*)&ks[d * KS_STRIDE + 2 * tx + 32 * b], acct[b]);
        }

        float e[14];
        #pragma unroll
        for (int b = 0; b < 7; b++) upk2(acct[b], e[2 * b], e[2 * b + 1]);

        bool v6 = (tx < 2);
        float mx = -1e30f;
        #pragma unroll
        for (int b = 0; b < 6; b++) mx = fmaxf(mx, fmaxf(e[2 * b], e[2 * b + 1]));
        if (v6) mx = fmaxf(mx, fmaxf(e[12], e[13]));
        #pragma unroll
        for (int off = 8; off > 0; off >>= 1)
            mx = fmaxf(mx, __shfl_xor_sync(0xffffffffu, mx, off));

        float s = 0.f;
        #pragma unroll
        for (int b = 0; b < 6; b++) {
            e[2 * b]     = __expf(e[2 * b] - mx);
            e[2 * b + 1] = __expf(e[2 * b + 1] - mx);
            s += e[2 * b] + e[2 * b + 1];
        }
        if (v6) {
            e[12] = __expf(e[12] - mx);
            e[13] = __expf(e[13] - mx);
            s += e[12] + e[13];
        }
        #pragma unroll
        for (int off = 8; off > 0; off >>= 1)
            s += __shfl_xor_sync(0xffffffffu, s, off);

        float inv = (1.f / 12.f) / s;
        u64 pv[7];
        #pragma unroll
        for (int b = 0; b < 7; b++)
            pv[b] = pk2(e[2 * b] * inv, e[2 * b + 1] * inv);
        // shfl must be warp-uniform: all lanes run it; only ty<4 lanes store.
        #pragma unroll
        for (int b = 0; b < 7; b++) {
            u64 nb = __shfl_down_sync(0xffffffffu, pv[b], 1);
            if (ty < 4 && (tx & 1) == 0 && (b < 6 || tx == 0)) {
                float a0, a1, b0, b1;
                upk2(pv[b], a0, a1);
                upk2(nb,    b0, b1);
                red4(P + (size_t)(192 + ty) * LL + 32 * b + 2 * tx, a0, a1, b0, b1);
            }
        }
    }
}

// ---------------------------------------------------------------------------
// Kernel 2 (fused halves, np-merged) — EXACT ROUND-8 VERSION (protected win).
// ---------------------------------------------------------------------------
#define TCo 64
#define WS_FLOATS (98 * TCo)            // 6272
#define PS_FLOATS (4 * LL * 8)          // 6272 per half (4 n)
#define O_SMEM_BYTES ((WS_FLOATS + 2 * PS_FLOATS) * 4)   // 75264 B

__global__ __launch_bounds__(256, 3)
void out_kernel(const float* __restrict__ w1, const float* __restrict__ w2,
                float* __restrict__ out) {
    extern __shared__ float sm[];
    float* ws  = sm;                    // [98][64]
    float* psA = sm + WS_FLOATS;        // [4][196*8]  slot tt = P1[t=tt-1], slot0=0
    float* psB = psA + PS_FLOATS;       // [4][196*8]  slot tt = P2[tt],    slot7=0

    int qq = blockIdx.y;
    int c0 = blockIdx.x * TCo;
    int tid = threadIdx.x;
    int pi = qq / 14, pj = qq - pi * 14;

    #pragma unroll
    for (int r = 0; r < 28; r++) {
        int n_l = r / 7, t = r - n_l * 7;
        if (tid < LL) {
            size_t base = ((size_t)(n_l * 7 + t) * LL + qq) * LL + tid;
            psA[n_l * (LL * 8) + tid * 8 + t + 1] = g_P1[base];
            psB[n_l * (LL * 8) + tid * 8 + t]     = g_P2[base];
        }
    }
    if (tid < LL) {
        #pragma unroll
        for (int n_l = 0; n_l < 4; n_l++) {
            psA[n_l * (LL * 8) + tid * 8] = 0.f;
            psB[n_l * (LL * 8) + tid * 8 + 7] = 0.f;
        }
    }

    int wid = tid >> 5, lane = tid & 31;
    int n_l = wid >> 1, kq = wid & 1;
    int sub = lane >> 4, cl = lane & 15;
    int kst = kq * 49;

    u64 acc[8];
    #pragma unroll
    for (int i = 0; i < 8; i++) acc[i] = 0ULL;

    #pragma unroll
    for (int ph = 0; ph < 4; ph++) {
        const float* w = (ph < 2) ? w1 : w2;
        const float* ps = ((ph < 2) ? psA : psB) + n_l * (LL * 8);
        int kbase = (ph & 1) * 98;

        __syncthreads();
        for (int i = tid; i < 98 * 16; i += 256) {
            int kk = i >> 4, cq = i & 15;
            int kg = kbase + kk;
            int ki = kg / 14, kj = kg - ki * 14;
            int idx = (pi - ki + 13) * 27 + (pj - kj + 13);
            *(float4*)&ws[kk * TCo + cq * 4] =
                *(const float4*)(w + (size_t)idx * CC + c0 + cq * 4);
        }
        __syncthreads();

        #pragma unroll 7
        for (int kl = kst; kl < kst + 49; kl++) {
            float4 wv = *(const float4*)&ws[kl * TCo + cl * 4];
            ulonglong2 pp = *(const ulonglong2*)&ps[(kbase + kl) * 8 + sub * 4];
            u64 b0 = pk2(wv.x, wv.x), b1 = pk2(wv.y, wv.y);
            u64 b2 = pk2(wv.z, wv.z), b3 = pk2(wv.w, wv.w);
            acc[0] = ffma2(pp.x, b0, acc[0]);  acc[1] = ffma2(pp.y, b0, acc[1]);
            acc[2] = ffma2(pp.x, b1, acc[2]);  acc[3] = ffma2(pp.y, b1, acc[3]);
            acc[4] = ffma2(pp.x, b2, acc[4]);  acc[5] = ffma2(pp.y, b2, acc[5]);
            acc[6] = ffma2(pp.x, b3, acc[6]);  acc[7] = ffma2(pp.y, b3, acc[7]);
        }
    }

    __syncthreads();
    u64* red = (u64*)ws;
    if (kq) {
        int base = (n_l * 32 + lane) * 8;
        #pragma unroll
        for (int j = 0; j < 8; j++) red[base + j] = acc[j];
    }
    __syncthreads();

    if (kq == 0) {
        int base = (n_l * 32 + lane) * 8;
        #pragma unroll
        for (int j = 0; j < 8; j++) acc[j] = fadd2(acc[j], red[base + j]);

        float a[16];
        #pragma unroll
        for (int i = 0; i < 8; i++) upk2(acc[i], a[2 * i], a[2 * i + 1]);
        #pragma unroll
        for (int tl = 0; tl < 4; tl++) {
            int tt = sub * 4 + tl;
            int tp = tl >> 1, hi = tl & 1;
            float4 o4;
            o4.x = a[(0 * 2 + tp) * 2 + hi];
            o4.y = a[(1 * 2 + tp) * 2 + hi];
            o4.z = a[(2 * 2 + tp) * 2 + hi];
            o4.w = a[(3 * 2 + tp) * 2 + hi];
            *(float4*)(out + ((size_t)(n_l * TDIM + tt) * LP1 + qq + 1) * CC
                       + c0 + cl * 4) = o4;
        }
    }
}

// ---------------------------------------------------------------------------
extern "C" void kernel_launch(void* const* d_in, const int* in_sizes, int n_in,
                              void* d_out, int out_size) {
    const float* q  = (const float*)d_in[0];
    const float* k  = (const float*)d_in[1];
    const float* w1 = (const float*)d_in[2];
    const float* w2 = (const float*)d_in[3];
    float* out = (float*)d_out;

    cudaFuncSetAttribute(attn_kernel, cudaFuncAttributeMaxDynamicSharedMemorySize, A_SMEM_BYTES);
    cudaFuncSetAttribute(out_kernel,  cudaFuncAttributeMaxDynamicSharedMemorySize, O_SMEM_BYTES);

    zero_kernel<<<512, 256>>>(out);
    attn_kernel<<<dim3(HH, NT, 6), 256, A_SMEM_BYTES>>>(q, k);
    out_kernel<<<dim3(CC / TCo, LL, 1), 256, O_SMEM_BYTES>>>(w1, w2, out);
}